// round 8
// baseline (speedup 1.0000x reference)
#include <cuda_runtime.h>
#include <cuda_bf16.h>

#define BATCH 8
#define NBOX 2048
#define MAXDET 100
#define THREADS 256
#define PER (NBOX / THREADS)   // 8 boxes per thread
#define NWARP (THREADS / 32)   // 8 warps
#define MIN_SIZE 25.0f
#define SCORE_THR 0.001f
#define DEAD -1.0f
#define CIOU 0.23076923f       // 0.3/1.3 : iou>0.3 <=> inter > CIOU*(A+B)

typedef unsigned long long u64;

// pack (score, idx): larger packed == (higher score, then smaller idx)
__device__ __forceinline__ u64 pack_si(float s, int idx) {
    return ((u64)__float_as_uint(s) << 32) | (unsigned)(~idx);
}

// merge two desc-sorted triples -> desc-sorted top-3 of the union (into a)
__device__ __forceinline__ void merge_top3(u64& a1, u64& a2, u64& a3,
                                           u64 b1, u64 b2, u64 b3) {
    bool gA = a1 > b1;
    u64 r1 = gA ? a1 : b1;
    u64 x1 = gA ? a2 : b2, x2 = gA ? a3 : b3;
    u64 y1 = gA ? b1 : a1, y2 = gA ? b2 : a2;
    bool g2 = x1 > y1;
    u64 r2 = g2 ? x1 : y1;
    u64 r3 = g2 ? (x2 > y1 ? x2 : y1) : (x1 > y2 ? x1 : y2);
    a1 = r1; a2 = r2; a3 = r3;
}

__device__ __forceinline__ float ciou_area(float4 b) {
    return CIOU * ((b.z - b.x) * (b.w - b.y));
}
__device__ __forceinline__ float inter_of(float4 a, float4 b) {
    float ix = fminf(a.z, b.z) - fmaxf(a.x, b.x);
    float iy = fminf(a.w, b.w) - fmaxf(a.y, b.y);
    return fmaxf(ix, 0.f) * fmaxf(iy, 0.f);
}

__global__ __launch_bounds__(THREADS, 1)
void nms_kernel(const float* __restrict__ boxes,
                const float* __restrict__ scores,
                float* __restrict__ out,
                int write_mask)
{
    __shared__ float4 sbox[NBOX];              // broadcast table (32 KB)
    __shared__ u64 ws[2][NWARP * 3];           // [parity][warp*3 + {0,1,2}]

    const int img  = blockIdx.x;
    const int tid  = threadIdx.x;
    const int warp = tid >> 5;
    const int lane = tid & 31;

    const float4* bp = (const float4*)(boxes + (size_t)img * NBOX * 4);
    const float*  sp = scores + (size_t)img * NBOX;

    float4 mybox[PER];
    float  mys[PER];
    float  myca[PER];
    #pragma unroll
    for (int p = 0; p < PER; p++) {
        int i = p * THREADS + tid;
        float4 b = bp[i];
        float  s = sp[i];
        float w = b.z - b.x;
        float h = b.w - b.y;
        bool valid = (w >= MIN_SIZE) && (h >= MIN_SIZE) && (s >= SCORE_THR);
        sbox[i]   = b;
        mybox[p]  = b;
        myca[p]   = CIOU * (w * h);
        mys[p]    = valid ? s : DEAD;
    }

    // init output padding: [img,0,0,0,0] rows, mask = 0
    float* outr = out + (size_t)img * MAXDET * 5;
    float* outm = out + (size_t)BATCH * MAXDET * 5 + (size_t)img * MAXDET;
    #pragma unroll
    for (int i = tid; i < MAXDET; i += THREADS) {
        outr[i * 5 + 0] = (float)img;
        outr[i * 5 + 1] = 0.f;
        outr[i * 5 + 2] = 0.f;
        outr[i * 5 + 3] = 0.f;
        outr[i * 5 + 4] = 0.f;
        if (write_mask) outm[i] = 0.f;
    }

    // prologue: thread-local exact top-3 (ascending idx + strict > = min-idx ties)
    float t1 = 0.f, t2 = 0.f, t3 = 0.f; int j1 = 0, j2 = 0, j3 = 0;
    #pragma unroll
    for (int p = 0; p < PER; p++) {
        float s = mys[p]; int idx = p * THREADS + tid;
        bool a = s > t1, b = s > t2, c = s > t3;
        float n1 = a ? s : t1;              int m1 = a ? idx : j1;
        float n2 = a ? t1 : (b ? s : t2);   int m2 = a ? j1 : (b ? idx : j2);
        float n3 = b ? t2 : (c ? s : t3);   int m3 = b ? j2 : (c ? idx : j3);
        t1 = n1; t2 = n2; t3 = n3; j1 = m1; j2 = m2; j3 = m3;
    }
    u64 lp1 = (t1 > 0.f) ? pack_si(t1, j1) : 0ULL;
    u64 lp2 = (t2 > 0.f) ? pack_si(t2, j2) : 0ULL;
    u64 lp3 = (t3 > 0.f) ? pack_si(t3, j3) : 0ULL;

    int k = 0, par = 0;
    while (k < MAXDET) {
        // warp-level exact top-3 butterfly
        u64 m1 = lp1, m2 = lp2, m3 = lp3;
        #pragma unroll
        for (int off = 16; off > 0; off >>= 1) {
            u64 o1 = __shfl_xor_sync(0xffffffffu, m1, off);
            u64 o2 = __shfl_xor_sync(0xffffffffu, m2, off);
            u64 o3 = __shfl_xor_sync(0xffffffffu, m3, off);
            merge_top3(m1, m2, m3, o1, o2, o3);
        }
        if (lane == 0) {
            ws[par][warp * 3 + 0] = m1;
            ws[par][warp * 3 + 1] = m2;
            ws[par][warp * 3 + 2] = m3;
        }
        __syncthreads();

        // merge warp triples -> exact global top-3 (redundant per thread)
        u64 g1 = 0ULL, g2 = 0ULL, g3 = 0ULL;
        #pragma unroll
        for (int j = 0; j < NWARP; j++)
            merge_top3(g1, g2, g3, ws[par][3 * j], ws[par][3 * j + 1], ws[par][3 * j + 2]);
        par ^= 1;

        if (g1 == 0ULL) break;                     // nothing live (uniform)

        float4 cb1 = sbox[(int)~(unsigned)(g1 & 0xffffffffu)];
        float ca1 = ciou_area(cb1);

        bool has2 = (g2 != 0ULL), has3 = (g3 != 0ULL);
        float4 cb2 = has2 ? sbox[(int)~(unsigned)(g2 & 0xffffffffu)] : cb1;
        float4 cb3 = has3 ? sbox[(int)~(unsigned)(g3 & 0xffffffffu)] : cb1;
        float ca2 = ciou_area(cb2);
        float ca3 = ciou_area(cb3);

        // verify speculative picks (exact greedy semantics)
        bool ok12 = !(inter_of(cb1, cb2) > ca1 + ca2);
        bool ok13 = !(inter_of(cb1, cb3) > ca1 + ca3);
        bool ok23 = !(inter_of(cb2, cb3) > ca2 + ca3);
        bool sel2 = has2 && ok12;
        bool sel3 = has3 && ok13 && (!sel2 || ok23);

        if (!sel2) { cb2 = cb1; ca2 = ca1; }       // alias rejected -> idempotent
        if (!sel3) { cb3 = cb1; ca3 = ca1; }

        if (tid == 0) {
            outr[k * 5 + 1] = cb1.x;
            outr[k * 5 + 2] = cb1.y;
            outr[k * 5 + 3] = cb1.z;
            outr[k * 5 + 4] = cb1.w;
            if (write_mask) outm[k] = 1.f;
            int kk = k + 1;
            if (sel2 && kk < MAXDET) {
                outr[kk * 5 + 1] = cb2.x;
                outr[kk * 5 + 2] = cb2.y;
                outr[kk * 5 + 3] = cb2.z;
                outr[kk * 5 + 4] = cb2.w;
                if (write_mask) outm[kk] = 1.f;
                kk++;
            }
            if (sel3 && kk < MAXDET) {
                outr[kk * 5 + 1] = cb3.x;
                outr[kk * 5 + 2] = cb3.y;
                outr[kk * 5 + 3] = cb3.z;
                outr[kk * 5 + 4] = cb3.w;
                if (write_mask) outm[kk] = 1.f;
            }
        }

        // fused: triple suppression + next thread-local top-3
        t1 = 0.f; t2 = 0.f; t3 = 0.f; j1 = 0; j2 = 0; j3 = 0;
        #pragma unroll
        for (int p = 0; p < PER; p++) {
            float4 b = mybox[p];
            // dead iff max_i(inter_i - ca_i) > CIOU*areaB
            float d1 = inter_of(cb1, b) - ca1;
            float d2 = inter_of(cb2, b) - ca2;
            float d3 = inter_of(cb3, b) - ca3;
            bool dead = fmaxf(d1, fmaxf(d2, d3)) > myca[p];
            float s = dead ? DEAD : mys[p];
            mys[p] = s;
            int idx = p * THREADS + tid;
            bool a = s > t1, bb = s > t2, c = s > t3;
            float n1 = a ? s : t1;               int m1i = a ? idx : j1;
            float n2 = a ? t1 : (bb ? s : t2);   int m2i = a ? j1 : (bb ? idx : j2);
            float n3 = bb ? t2 : (c ? s : t3);   int m3i = bb ? j2 : (c ? idx : j3);
            t1 = n1; t2 = n2; t3 = n3; j1 = m1i; j2 = m2i; j3 = m3i;
        }
        lp1 = (t1 > 0.f) ? pack_si(t1, j1) : 0ULL;
        lp2 = (t2 > 0.f) ? pack_si(t2, j2) : 0ULL;
        lp3 = (t3 > 0.f) ? pack_si(t3, j3) : 0ULL;

        k += 1 + (sel2 ? 1 : 0) + (sel3 ? 1 : 0);
    }
}

extern "C" void kernel_launch(void* const* d_in, const int* in_sizes, int n_in,
                              void* d_out, int out_size) {
    const float* boxes  = (const float*)d_in[0];   // [8,2048,4] f32
    const float* scores = (const float*)d_in[1];   // [8,2048]   f32
    float* out = (float*)d_out;
    int write_mask = (out_size >= BATCH * MAXDET * 5 + BATCH * MAXDET) ? 1 : 0;
    nms_kernel<<<BATCH, THREADS>>>(boxes, scores, out, write_mask);
}

// round 9
// speedup vs baseline: 1.3184x; 1.3184x over previous
#include <cuda_runtime.h>
#include <cuda_bf16.h>

#define BATCH 8
#define NBOX 2048
#define MAXDET 100
#define THREADS 128
#define PER (NBOX / THREADS)   // 16 boxes per thread
#define MIN_SIZE 25.0f
#define SCORE_THR 0.001f
#define DEAD -1.0f
#define CIOU 0.23076923f       // 0.3/1.3 : iou>0.3 <=> inter > CIOU*(A+B)

typedef unsigned long long u64;

// pack (score, idx): larger packed == (higher score, then smaller idx)
__device__ __forceinline__ u64 pack_si(float s, int idx) {
    return ((u64)__float_as_uint(s) << 32) | (unsigned)(~idx);
}

// merge two desc-sorted triples -> desc-sorted top-3 of the union (into a)
__device__ __forceinline__ void merge_top3(u64& a1, u64& a2, u64& a3,
                                           u64 b1, u64 b2, u64 b3) {
    bool gA = a1 > b1;
    u64 r1 = gA ? a1 : b1;
    u64 x1 = gA ? a2 : b2, x2 = gA ? a3 : b3;
    u64 y1 = gA ? b1 : a1, y2 = gA ? b2 : a2;
    bool g2 = x1 > y1;
    u64 r2 = g2 ? x1 : y1;
    u64 r3 = g2 ? (x2 > y1 ? x2 : y1) : (x1 > y2 ? x1 : y2);
    a1 = r1; a2 = r2; a3 = r3;
}

__device__ __forceinline__ float ciou_area(float4 b) {
    return CIOU * ((b.z - b.x) * (b.w - b.y));
}
__device__ __forceinline__ float inter_of(float4 a, float4 b) {
    float ix = fminf(a.z, b.z) - fmaxf(a.x, b.x);
    float iy = fminf(a.w, b.w) - fmaxf(a.y, b.y);
    return fmaxf(ix, 0.f) * fmaxf(iy, 0.f);
}

// top-3 insert for one (s, idx): a/b/c desc-sorted
#define TOP3_INSERT(s, idx, t1, t2, t3, j1, j2, j3)                   \
    do {                                                              \
        bool _a = (s) > (t1), _b = (s) > (t2), _c = (s) > (t3);       \
        float _n1 = _a ? (s) : (t1);            int _m1 = _a ? (idx) : (j1); \
        float _n2 = _a ? (t1) : (_b ? (s) : (t2)); int _m2 = _a ? (j1) : (_b ? (idx) : (j2)); \
        float _n3 = _b ? (t2) : (_c ? (s) : (t3)); int _m3 = _b ? (j2) : (_c ? (idx) : (j3)); \
        t1 = _n1; t2 = _n2; t3 = _n3; j1 = _m1; j2 = _m2; j3 = _m3;   \
    } while (0)

__global__ __launch_bounds__(THREADS, 1)
void nms_kernel(const float* __restrict__ boxes,
                const float* __restrict__ scores,
                float* __restrict__ out,
                int write_mask)
{
    __shared__ float4 sbox[NBOX];            // broadcast table (32 KB)
    __shared__ u64 ws[2][12];                // [parity][warp*3 + {0,1,2}]

    const int img  = blockIdx.x;
    const int tid  = threadIdx.x;
    const int warp = tid >> 5;
    const int lane = tid & 31;

    const float4* bp = (const float4*)(boxes + (size_t)img * NBOX * 4);
    const float*  sp = scores + (size_t)img * NBOX;

    float4 mybox[PER];
    float  mys[PER];
    float  myca[PER];
    #pragma unroll
    for (int p = 0; p < PER; p++) {
        int i = p * THREADS + tid;
        float4 b = bp[i];
        float  s = sp[i];
        float w = b.z - b.x;
        float h = b.w - b.y;
        bool valid = (w >= MIN_SIZE) && (h >= MIN_SIZE) && (s >= SCORE_THR);
        sbox[i]   = b;
        mybox[p]  = b;
        myca[p]   = CIOU * (w * h);
        mys[p]    = valid ? s : DEAD;
    }

    // init output padding: [img,0,0,0,0] rows, mask = 0
    float* outr = out + (size_t)img * MAXDET * 5;
    float* outm = out + (size_t)BATCH * MAXDET * 5 + (size_t)img * MAXDET;
    #pragma unroll
    for (int i = tid; i < MAXDET; i += THREADS) {
        outr[i * 5 + 0] = (float)img;
        outr[i * 5 + 1] = 0.f;
        outr[i * 5 + 2] = 0.f;
        outr[i * 5 + 3] = 0.f;
        outr[i * 5 + 4] = 0.f;
        if (write_mask) outm[i] = 0.f;
    }

    // prologue: split-chain thread-local top-3 (strict > on ascending idx = min-idx ties)
    float ta1 = 0.f, ta2 = 0.f, ta3 = 0.f; int ja1 = 0, ja2 = 0, ja3 = 0;
    float tb1 = 0.f, tb2 = 0.f, tb3 = 0.f; int jb1 = 0, jb2 = 0, jb3 = 0;
    #pragma unroll
    for (int p = 0; p < PER; p += 2) {
        TOP3_INSERT(mys[p],     p * THREADS + tid,       ta1, ta2, ta3, ja1, ja2, ja3);
        TOP3_INSERT(mys[p + 1], (p + 1) * THREADS + tid, tb1, tb2, tb3, jb1, jb2, jb3);
    }
    u64 lp1 = (ta1 > 0.f) ? pack_si(ta1, ja1) : 0ULL;
    u64 lp2 = (ta2 > 0.f) ? pack_si(ta2, ja2) : 0ULL;
    u64 lp3 = (ta3 > 0.f) ? pack_si(ta3, ja3) : 0ULL;
    {
        u64 q1 = (tb1 > 0.f) ? pack_si(tb1, jb1) : 0ULL;
        u64 q2 = (tb2 > 0.f) ? pack_si(tb2, jb2) : 0ULL;
        u64 q3 = (tb3 > 0.f) ? pack_si(tb3, jb3) : 0ULL;
        merge_top3(lp1, lp2, lp3, q1, q2, q3);
    }

    int k = 0, par = 0;
    while (k < MAXDET) {
        // warp-level exact top-3 butterfly
        u64 m1 = lp1, m2 = lp2, m3 = lp3;
        #pragma unroll
        for (int off = 16; off > 0; off >>= 1) {
            u64 o1 = __shfl_xor_sync(0xffffffffu, m1, off);
            u64 o2 = __shfl_xor_sync(0xffffffffu, m2, off);
            u64 o3 = __shfl_xor_sync(0xffffffffu, m3, off);
            merge_top3(m1, m2, m3, o1, o2, o3);
        }
        if (lane == 0) {
            ws[par][warp * 3 + 0] = m1;
            ws[par][warp * 3 + 1] = m2;
            ws[par][warp * 3 + 2] = m3;
        }
        __syncthreads();

        // tree merge of 4 warp triples (independent loads, depth-2 merge)
        u64 a1 = ws[par][0], a2 = ws[par][1],  a3 = ws[par][2];
        u64 b1 = ws[par][3], b2 = ws[par][4],  b3 = ws[par][5];
        u64 c1 = ws[par][6], c2 = ws[par][7],  c3 = ws[par][8];
        u64 d1 = ws[par][9], d2 = ws[par][10], d3 = ws[par][11];
        merge_top3(a1, a2, a3, b1, b2, b3);
        merge_top3(c1, c2, c3, d1, d2, d3);
        merge_top3(a1, a2, a3, c1, c2, c3);
        par ^= 1;

        if (a1 == 0ULL) break;                     // nothing live (uniform)

        float4 cb1 = sbox[(int)~(unsigned)(a1 & 0xffffffffu)];
        bool has2 = (a2 != 0ULL), has3 = (a3 != 0ULL);
        float4 cb2 = has2 ? sbox[(int)~(unsigned)(a2 & 0xffffffffu)] : cb1;
        float4 cb3 = has3 ? sbox[(int)~(unsigned)(a3 & 0xffffffffu)] : cb1;
        float ca1 = ciou_area(cb1);
        float ca2 = ciou_area(cb2);
        float ca3 = ciou_area(cb3);

        // verify speculative picks (exact greedy semantics)
        bool ok12 = !(inter_of(cb1, cb2) > ca1 + ca2);
        bool ok13 = !(inter_of(cb1, cb3) > ca1 + ca3);
        bool ok23 = !(inter_of(cb2, cb3) > ca2 + ca3);
        bool sel2 = has2 && ok12;
        bool sel3 = has3 && ok13 && (!sel2 || ok23);

        if (!sel2) { cb2 = cb1; ca2 = ca1; }       // alias rejected -> idempotent
        if (!sel3) { cb3 = cb1; ca3 = ca1; }

        if (tid == 0) {
            outr[k * 5 + 1] = cb1.x;
            outr[k * 5 + 2] = cb1.y;
            outr[k * 5 + 3] = cb1.z;
            outr[k * 5 + 4] = cb1.w;
            if (write_mask) outm[k] = 1.f;
            int kk = k + 1;
            if (sel2 && kk < MAXDET) {
                outr[kk * 5 + 1] = cb2.x;
                outr[kk * 5 + 2] = cb2.y;
                outr[kk * 5 + 3] = cb2.z;
                outr[kk * 5 + 4] = cb2.w;
                if (write_mask) outm[kk] = 1.f;
                kk++;
            }
            if (sel3 && kk < MAXDET) {
                outr[kk * 5 + 1] = cb3.x;
                outr[kk * 5 + 2] = cb3.y;
                outr[kk * 5 + 3] = cb3.z;
                outr[kk * 5 + 4] = cb3.w;
                if (write_mask) outm[kk] = 1.f;
            }
        }

        // fused: triple suppression + split-chain thread-local top-3
        ta1 = 0.f; ta2 = 0.f; ta3 = 0.f; ja1 = 0; ja2 = 0; ja3 = 0;
        tb1 = 0.f; tb2 = 0.f; tb3 = 0.f; jb1 = 0; jb2 = 0; jb3 = 0;
        #pragma unroll
        for (int p = 0; p < PER; p += 2) {
            {
                float4 b = mybox[p];
                float d1 = inter_of(cb1, b) - ca1;
                float d2 = inter_of(cb2, b) - ca2;
                float d3 = inter_of(cb3, b) - ca3;
                bool dd = fmaxf(d1, fmaxf(d2, d3)) > myca[p];
                float s = dd ? DEAD : mys[p];
                mys[p] = s;
                TOP3_INSERT(s, p * THREADS + tid, ta1, ta2, ta3, ja1, ja2, ja3);
            }
            {
                float4 b = mybox[p + 1];
                float d1 = inter_of(cb1, b) - ca1;
                float d2 = inter_of(cb2, b) - ca2;
                float d3 = inter_of(cb3, b) - ca3;
                bool dd = fmaxf(d1, fmaxf(d2, d3)) > myca[p + 1];
                float s = dd ? DEAD : mys[p + 1];
                mys[p + 1] = s;
                TOP3_INSERT(s, (p + 1) * THREADS + tid, tb1, tb2, tb3, jb1, jb2, jb3);
            }
        }
        lp1 = (ta1 > 0.f) ? pack_si(ta1, ja1) : 0ULL;
        lp2 = (ta2 > 0.f) ? pack_si(ta2, ja2) : 0ULL;
        lp3 = (ta3 > 0.f) ? pack_si(ta3, ja3) : 0ULL;
        {
            u64 q1 = (tb1 > 0.f) ? pack_si(tb1, jb1) : 0ULL;
            u64 q2 = (tb2 > 0.f) ? pack_si(tb2, jb2) : 0ULL;
            u64 q3 = (tb3 > 0.f) ? pack_si(tb3, jb3) : 0ULL;
            merge_top3(lp1, lp2, lp3, q1, q2, q3);
        }

        k += 1 + (sel2 ? 1 : 0) + (sel3 ? 1 : 0);
    }
}

extern "C" void kernel_launch(void* const* d_in, const int* in_sizes, int n_in,
                              void* d_out, int out_size) {
    const float* boxes  = (const float*)d_in[0];   // [8,2048,4] f32
    const float* scores = (const float*)d_in[1];   // [8,2048]   f32
    float* out = (float*)d_out;
    int write_mask = (out_size >= BATCH * MAXDET * 5 + BATCH * MAXDET) ? 1 : 0;
    nms_kernel<<<BATCH, THREADS>>>(boxes, scores, out, write_mask);
}

// round 10
// speedup vs baseline: 1.6629x; 1.2613x over previous
#include <cuda_runtime.h>
#include <cuda_bf16.h>

#define BATCH 8
#define NBOX 2048
#define MAXDET 100
#define THREADS 128
#define EPT 16                      // sort: elements per thread (blocked)
#define MIN_SIZE 25.0f
#define SCORE_THR 0.001f
#define CIOU 0.23076923f            // 0.3/1.3 : iou>0.3 <=> inter > CIOU*(A+B)

typedef unsigned long long u64;
typedef unsigned int u32;

// key: (score bits << 32) | ~idx  -> descending sort == (score desc, idx asc)
__device__ __forceinline__ u64 pack_si(float s, int idx) {
    return ((u64)__float_as_uint(s) << 32) | (u32)(~idx);
}
__device__ __forceinline__ float ciou_area(float4 b) {
    return CIOU * ((b.z - b.x) * (b.w - b.y));
}
__device__ __forceinline__ float inter_of(float4 a, float4 b) {
    float ix = fminf(a.z, b.z) - fmaxf(a.x, b.x);
    float iy = fminf(a.w, b.w) - fmaxf(a.y, b.y);
    return fmaxf(ix, 0.f) * fmaxf(iy, 0.f);
}

extern __shared__ char smem_raw[];
// sbox f4[2048] | skey u64[2048] | pbox f4[100] | cbox f4[32]
// pca f[100] | cca f[32] | sdead u32[4] | smat8 u8[32*4]
#define SMEM_BYTES (32768 + 16384 + 1600 + 512 + 400 + 128 + 16 + 128 + 64)

__global__ __launch_bounds__(THREADS, 1)
void nms_kernel(const float* __restrict__ boxes,
                const float* __restrict__ scores,
                float* __restrict__ out,
                int write_mask)
{
    float4* sbox = (float4*)smem_raw;
    u64*    skey = (u64*)(sbox + NBOX);
    float4* pbox = (float4*)(skey + NBOX);
    float4* cbox = pbox + MAXDET;
    float*  pca  = (float*)(cbox + 32);
    float*  cca  = pca + MAXDET;
    u32*    sdead = (u32*)(cca + 32);
    unsigned char* smat8 = (unsigned char*)(sdead + 4);
    u32*    smat32 = (u32*)smat8;

    const int img  = blockIdx.x;
    const int tid  = threadIdx.x;
    const int warp = tid >> 5;
    const int lane = tid & 31;
    const int base = tid * EPT;

    // ---- load, validity filter, build keys (invalid -> 0) ----
    const float4* bp = (const float4*)(boxes + (size_t)img * NBOX * 4);
    const float*  sp = scores + (size_t)img * NBOX;
    #pragma unroll
    for (int p = 0; p < NBOX / THREADS; p++) {
        int i = p * THREADS + tid;
        float4 b = bp[i];
        float  s = sp[i];
        float w = b.z - b.x;
        float h = b.w - b.y;
        bool valid = (w >= MIN_SIZE) && (h >= MIN_SIZE) && (s >= SCORE_THR);
        sbox[i] = b;
        skey[i] = valid ? pack_si(s, i) : 0ULL;
    }

    // ---- init output padding: [img,0,0,0,0] rows, mask = 0 ----
    float* outr = out + (size_t)img * MAXDET * 5;
    float* outm = out + (size_t)BATCH * MAXDET * 5 + (size_t)img * MAXDET;
    #pragma unroll
    for (int i = tid; i < MAXDET; i += THREADS) {
        outr[i * 5 + 0] = (float)img;
        outr[i * 5 + 1] = 0.f;
        outr[i * 5 + 2] = 0.f;
        outr[i * 5 + 3] = 0.f;
        outr[i * 5 + 4] = 0.f;
        if (write_mask) outm[i] = 0.f;
    }
    __syncthreads();

    // ================= bitonic sort (descending), blocked-register hybrid ====
    u64 key[EPT];
    #pragma unroll
    for (int e = 0; e < EPT; e++) key[e] = skey[base + e];

    // presort k=2..16 entirely in registers
    #pragma unroll
    for (int k = 2; k <= 16; k <<= 1) {
        #pragma unroll
        for (int j = k >> 1; j > 0; j >>= 1) {
            #pragma unroll
            for (int e = 0; e < EPT; e++) {
                if ((e & j) == 0) {
                    int f = e | j;
                    bool up = (((base + e) & k) == 0);
                    u64 x = key[e], y = key[f];
                    bool sw = up ? (x < y) : (x > y);
                    if (sw) { key[e] = y; key[f] = x; }
                }
            }
        }
    }

    // k-phases 32..2048: shared stages for j>=16, register tail j<=8
    #pragma unroll 1
    for (int kk = 32; kk <= NBOX; kk <<= 1) {
        #pragma unroll
        for (int e = 0; e < EPT; e++) skey[base + e] = key[e];
        __syncthreads();
        #pragma unroll 1
        for (int j = kk >> 1; j >= 16; j >>= 1) {
            #pragma unroll
            for (int n = 0; n < NBOX / 2 / THREADS; n++) {
                int idx = tid + n * THREADS;
                int i1 = ((idx & ~(j - 1)) << 1) | (idx & (j - 1));
                int i2 = i1 | j;
                bool up = ((i1 & kk) == 0);
                u64 x = skey[i1], y = skey[i2];
                bool sw = up ? (x < y) : (x > y);
                if (sw) { skey[i1] = y; skey[i2] = x; }
            }
            __syncthreads();
        }
        #pragma unroll
        for (int e = 0; e < EPT; e++) key[e] = skey[base + e];
        {
            bool up = ((base & kk) == 0);
            #pragma unroll
            for (int j = 8; j > 0; j >>= 1) {
                #pragma unroll
                for (int e = 0; e < EPT; e++) {
                    if ((e & j) == 0) {
                        int f = e | j;
                        u64 x = key[e], y = key[f];
                        bool sw = up ? (x < y) : (x > y);
                        if (sw) { key[e] = y; key[f] = x; }
                    }
                }
            }
        }
    }
    // final write-back: sorted keys to shared for the batch engine
    #pragma unroll
    for (int e = 0; e < EPT; e++) skey[base + e] = key[e];
    __syncthreads();

    // ================= lazy greedy: batch-verified walk in rank order ========
    int npicks = 0;
    int rb = 0;
    while (rb < NBOX && npicks < MAXDET) {
        if (skey[rb] == 0ULL) break;           // all remaining invalid (uniform)

        // stage candidate boxes (ranks rb..rb+31)
        if (tid < 32) {
            u64 kkey = skey[rb + tid];
            int idx = (int)(~(u32)kkey) & (NBOX - 1);
            float4 b = sbox[idx];
            cbox[tid] = b;
            cca[tid]  = ciou_area(b);
        }
        __syncthreads();

        float4 myb = cbox[lane];               // candidate = lane
        float  mya = cca[lane];

        // (a) candidate vs existing picks (picks strided over 4 warps)
        bool dead = false;
        for (int j = warp; j < npicks; j += 4) {
            float4 pb = pbox[j];               // broadcast within warp
            dead |= inter_of(pb, myb) > pca[j] + mya;
        }
        u32 bal = __ballot_sync(0xffffffffu, dead);
        if (lane == 0) sdead[warp] = bal;

        // (b) 32x32 pairwise overlap matrix: row=lane, cols warp*8..warp*8+7
        u32 bits8 = 0;
        #pragma unroll
        for (int q = 0; q < 8; q++) {
            int c = warp * 8 + q;
            float4 ob = cbox[c];               // broadcast within warp
            bool ov = inter_of(myb, ob) > mya + cca[c];
            bits8 |= (ov ? 1u : 0u) << q;
        }
        smat8[lane * 4 + warp] = (unsigned char)bits8;   // conflict-free
        __syncthreads();

        u32 deadP = sdead[0] | sdead[1] | sdead[2] | sdead[3];

        // (c) exact in-batch greedy walk (redundant, uniform across threads)
        u32 acc = 0;
        #pragma unroll
        for (int j = 0; j < 32; j++) {
            u64 kj  = skey[rb + j];
            u32 row = smat32[j];               // symmetric matrix: row == column
            bool take = (kj != 0ULL) && !((deadP >> j) & 1u) && ((acc & row) == 0u);
            if (take) acc |= 1u << j;
        }

        // (d) append accepted picks + write output rows
        if (tid < 32 && ((acc >> tid) & 1u)) {
            int slot = npicks + __popc(acc & ((1u << tid) - 1u));
            if (slot < MAXDET) {
                float4 b = cbox[tid];
                pbox[slot] = b;
                pca[slot]  = cca[tid];
                float* row = outr + slot * 5;
                row[1] = b.x; row[2] = b.y; row[3] = b.z; row[4] = b.w;
                if (write_mask) outm[slot] = 1.f;
            }
        }
        npicks = min(npicks + __popc(acc), MAXDET);
        rb += 32;
        __syncthreads();                       // pbox/pca visible; cbox reusable
    }
}

extern "C" void kernel_launch(void* const* d_in, const int* in_sizes, int n_in,
                              void* d_out, int out_size) {
    const float* boxes  = (const float*)d_in[0];   // [8,2048,4] f32
    const float* scores = (const float*)d_in[1];   // [8,2048]   f32
    float* out = (float*)d_out;
    int write_mask = (out_size >= BATCH * MAXDET * 5 + BATCH * MAXDET) ? 1 : 0;

    static int attr_done = 0;
    if (!attr_done) {
        cudaFuncSetAttribute(nms_kernel,
                             cudaFuncAttributeMaxDynamicSharedMemorySize,
                             SMEM_BYTES);
        attr_done = 1;
    }
    nms_kernel<<<BATCH, THREADS, SMEM_BYTES>>>(boxes, scores, out, write_mask);
}